// round 16
// baseline (speedup 1.0000x reference)
#include <cuda_runtime.h>
#include <math.h>
#include <stdint.h>

#define B_ 2
#define S_ 2048
#define D_ 1024
#define H_ 16
#define DEPTH_ 64
#define DFF_ 4096
#define NT_ (B_ * S_)
#define EPS_ 1e-5f
#define LDQKV_ 3072
#define NROWS_ (B_ * H_ * S_)
#define NKT_ 16

// ---------------- scratch ----------------
__device__ float g_qkv[NT_ * LDQKV_];
__device__ float g_wcat[D_ * LDQKV_];   // WqkvT [3072][1024]
__device__ float g_bcat[LDQKV_];
__device__ float g_ctx[NT_ * D_];
__device__ float g_ao [NT_ * D_];
__device__ float g_x1 [NT_ * D_];
__device__ float g_x1r[NT_ * D_];
__device__ float g_h1 [NT_ * DFF_];
__device__ float g_ff2[NT_ * D_];
__device__ float g_xr [NT_ * D_];
__device__ float g_wr [9437184];        // WoT(1M) W1T(4M) W2T(4M)
__device__ float g_rs [NROWS_ * NKT_];

// ---------------- helpers ----------------
__device__ __forceinline__ unsigned f2tf(float x) {
    unsigned r;
    asm("cvt.rna.tf32.f32 %0, %1;" : "=r"(r) : "f"(x));
    return r;
}
__device__ __forceinline__ float roundtf(float x) { return __uint_as_float(f2tf(x)); }

__device__ __forceinline__ void mma_tf32(float c[4],
                                         unsigned a0, unsigned a1, unsigned a2, unsigned a3,
                                         unsigned b0, unsigned b1) {
    asm volatile(
        "mma.sync.aligned.m16n8k8.row.col.f32.tf32.tf32.f32 "
        "{%0,%1,%2,%3},{%4,%5,%6,%7},{%8,%9},{%0,%1,%2,%3};\n"
        : "+f"(c[0]), "+f"(c[1]), "+f"(c[2]), "+f"(c[3])
        : "r"(a0), "r"(a1), "r"(a2), "r"(a3), "r"(b0), "r"(b1));
}

__device__ __forceinline__ void ldsm_x4(unsigned &r0, unsigned &r1, unsigned &r2, unsigned &r3,
                                        uint32_t addr) {
    asm volatile("ldmatrix.sync.aligned.m8n8.x4.shared.b16 {%0,%1,%2,%3}, [%4];"
                 : "=r"(r0), "=r"(r1), "=r"(r2), "=r"(r3) : "r"(addr));
}

__device__ __forceinline__ void cp16(void* smem, const void* gmem) {
    unsigned sa = (unsigned)__cvta_generic_to_shared(smem);
    asm volatile("cp.async.cg.shared.global [%0], [%1], 16;\n" :: "r"(sa), "l"(gmem));
}
#define CP_COMMIT() asm volatile("cp.async.commit_group;\n" ::)
#define CP_WAIT1()  asm volatile("cp.async.wait_group 1;\n" ::)
#define CP_WAIT0()  asm volatile("cp.async.wait_group 0;\n" ::)

__device__ __forceinline__ uint32_t smem_u32(const void* p) {
    return (uint32_t)__cvta_generic_to_shared(p);
}

// =====================================================================
// prep_all: ALL weight transposes + x rounding in ONE launch. (verified R15)
// =====================================================================
__global__ void prep_all(const float* __restrict__ Wq, const float* __restrict__ Wk,
                         const float* __restrict__ Wv, const float* __restrict__ Wo,
                         const float* __restrict__ W1, const float* __restrict__ W2,
                         const float* __restrict__ x,
                         float* __restrict__ WqkvT, float* __restrict__ WoT,
                         float* __restrict__ W1T,  float* __restrict__ W2T,
                         float* __restrict__ xr) {
    const int bid = blockIdx.x;
    const int tx = threadIdx.x, ty = threadIdx.y;

    if (bid >= 12288) {
        int t = bid - 12288;
        int i = t * 256 + ty * 32 + tx;
        float4 v = ((const float4*)x)[i];
        v.x = roundtf(v.x); v.y = roundtf(v.y); v.z = roundtf(v.z); v.w = roundtf(v.w);
        ((float4*)xr)[i] = v;
        return;
    }

    const float* src; float* dst; int R, C, c0, r0;
    if (bid < 4096) {
        int which = bid >> 10, t = bid & 1023;
        const float* srcs[4] = {Wq, Wk, Wv, Wo};
        float* dsts[4] = {WqkvT, WqkvT + 1048576, WqkvT + 2097152, WoT};
        src = srcs[which]; dst = dsts[which];
        R = 1024; C = 1024; c0 = (t & 31) * 32; r0 = (t >> 5) * 32;
    } else if (bid < 8192) {
        int t = bid - 4096;
        src = W1; dst = W1T;
        R = 1024; C = 4096; c0 = (t & 127) * 32; r0 = (t >> 7) * 32;
    } else {
        int t = bid - 8192;
        src = W2; dst = W2T;
        R = 4096; C = 1024; c0 = (t & 31) * 32; r0 = (t >> 5) * 32;
    }

    __shared__ float tb[32][33];
    #pragma unroll
    for (int i = 0; i < 4; i++)
        tb[ty + i * 8][tx] = src[(size_t)(r0 + ty + i * 8) * C + c0 + tx];
    __syncthreads();
    #pragma unroll
    for (int i = 0; i < 4; i++)
        dst[(size_t)(c0 + ty + i * 8) * R + r0 + tx] = roundtf(tb[tx][ty + i * 8]);
}

// =====================================================================
// Dense GEMM: K-tile 32, 2-stage cp.async, 128x128, ldmatrix. (verified)
// =====================================================================
#define ASZ_ 4608
#define BSZ_ 4608
#define LDK_ 36
template <int GELU, int ROUND>
__global__ __launch_bounds__(256, 2)
void gemm_tf32p(const float* __restrict__ A, const float* __restrict__ Bt,
                const float* __restrict__ bias, float* __restrict__ C,
                int M, int N, int K) {
    extern __shared__ unsigned dsm[];
    unsigned* Asp = dsm;
    unsigned* Bsp = dsm + 2 * ASZ_;
    const uint32_t sA0 = smem_u32(Asp), sB0 = smem_u32(Bsp);

    const int tid = threadIdx.x;
    const int warp = tid >> 5, lane = tid & 31;
    const int g = lane >> 2, tg = lane & 3;
    const int m0 = blockIdx.y * 128, n0 = blockIdx.x * 128;
    const int wm = (warp >> 1) * 32, wn = (warp & 1) * 64;

    const int a_row = wm + (lane & 15);
    const int a_col = (lane >> 4) * 4;
    const int b_row = (lane & 7) + ((lane >> 4) & 1) * 8;
    const int b_col = ((lane >> 3) & 1) * 4;

    const int rL = tid >> 3, kcL = (tid & 7) * 4;

    float c[2][8][4] = {};
    const int T = K >> 5;

    #pragma unroll
    for (int i = 0; i < 4; i++) {
        cp16(&Asp[(rL + i * 32) * LDK_ + kcL], &A[(size_t)(m0 + rL + i * 32) * K + kcL]);
        cp16(&Bsp[(rL + i * 32) * LDK_ + kcL], &Bt[(size_t)(n0 + rL + i * 32) * K + kcL]);
    }
    CP_COMMIT();

    for (int t = 0; t < T; t++) {
        if (t + 1 < T) {
            const int s = (t + 1) & 1, k0 = (t + 1) << 5;
            #pragma unroll
            for (int i = 0; i < 4; i++) {
                cp16(&Asp[s * ASZ_ + (rL + i * 32) * LDK_ + kcL],
                     &A[(size_t)(m0 + rL + i * 32) * K + k0 + kcL]);
                cp16(&Bsp[s * BSZ_ + (rL + i * 32) * LDK_ + kcL],
                     &Bt[(size_t)(n0 + rL + i * 32) * K + k0 + kcL]);
            }
            CP_COMMIT();
            CP_WAIT1();
        } else {
            CP_WAIT0();
        }
        __syncthreads();
        const uint32_t sA = sA0 + (t & 1) * ASZ_ * 4;
        const uint32_t sB = sB0 + (t & 1) * BSZ_ * 4;
        #pragma unroll
        for (int ks = 0; ks < 32; ks += 8) {
            unsigned a[2][4], b[8][2];
            #pragma unroll
            for (int i = 0; i < 2; i++)
                ldsm_x4(a[i][0], a[i][1], a[i][2], a[i][3],
                        sA + (uint32_t)(((a_row + i * 16) * LDK_ + ks + a_col) * 4));
            #pragma unroll
            for (int jj = 0; jj < 4; jj++)
                ldsm_x4(b[2 * jj][0], b[2 * jj][1], b[2 * jj + 1][0], b[2 * jj + 1][1],
                        sB + (uint32_t)(((wn + jj * 16 + b_row) * LDK_ + ks + b_col) * 4));
            #pragma unroll
            for (int i = 0; i < 2; i++)
                #pragma unroll
                for (int j = 0; j < 8; j++)
                    mma_tf32(c[i][j], a[i][0], a[i][1], a[i][2], a[i][3], b[j][0], b[j][1]);
        }
        __syncthreads();
    }

    #pragma unroll
    for (int i = 0; i < 2; i++) {
        #pragma unroll
        for (int j = 0; j < 8; j++) {
            int col = n0 + wn + j * 8 + tg * 2;
            float b0v = bias[col], b1v = bias[col + 1];
            #pragma unroll
            for (int h = 0; h < 2; h++) {
                int row = m0 + wm + i * 16 + g + h * 8;
                float v0 = c[i][j][h * 2 + 0] + b0v;
                float v1 = c[i][j][h * 2 + 1] + b1v;
                if (GELU) {
                    v0 = 0.5f * v0 * (1.0f + erff(v0 * 0.70710678118654752f));
                    v1 = 0.5f * v1 * (1.0f + erff(v1 * 0.70710678118654752f));
                }
                if (ROUND) { v0 = roundtf(v0); v1 = roundtf(v1); }
                *(float2*)&C[(size_t)row * N + col] = make_float2(v0, v1);
            }
        }
    }
}

// =====================================================================
// Scores + exp + partial row sums; kt>qt blocks zero-fill.
// 2-stage load pipeline over two 32-col DEPTH chunks.
// smem: Qs[2][128][36] + Ks[2][128][36] = 73728 B dynamic.
// =====================================================================
#define SCQ_ 4608   // 128*36
__global__ __launch_bounds__(256, 2)
void attn_scores_exp(const float* __restrict__ QKV, float* __restrict__ attnP,
                     float* __restrict__ rs) {
    const int kt = blockIdx.x, qt = blockIdx.y, bh = blockIdx.z;
    const int tid = threadIdx.x;

    if (kt > qt) {
        float4 z = make_float4(0.f, 0.f, 0.f, 0.f);
        float* tb = attnP + ((size_t)bh * S_ + qt * 128) * S_ + kt * 128;
        #pragma unroll
        for (int e = 0; e < 16; e++) {
            int u = tid + e * 256;
            int r = u >> 5, c4 = u & 31;
            ((float4*)(tb + (size_t)r * S_))[c4] = z;
        }
        return;
    }

    const int b = bh >> 4, h = bh & 15;

    extern __shared__ unsigned dsm[];
    unsigned* Qs = dsm;                     // [2][128][36]
    unsigned* Ks = dsm + 2 * SCQ_;          // [2][128][36]
    const uint32_t sQ0 = smem_u32(Qs), sK0 = smem_u32(Ks);

    const int warp = tid >> 5, lane = tid & 31;
    const int g = lane >> 2, tg = lane & 3;
    const int wm = (warp >> 1) * 32, wn = (warp & 1) * 64;

    const int a_row = wm + (lane & 15);
    const int a_col = (lane >> 4) * 4;
    const int b_row = (lane & 7) + ((lane >> 4) & 1) * 8;
    const int b_col = ((lane >> 3) & 1) * 4;

    const float* qb = QKV + (size_t)(b * S_ + qt * 128) * LDQKV_ + h * DEPTH_;
    const float* kb = QKV + (size_t)(b * S_ + kt * 128) * LDQKV_ + 1024 + h * DEPTH_;

    const int rL = tid >> 3, kcL = (tid & 7) * 4;

    // prologue: both chunks (chunk c covers cols c*32..c*32+31)
    #pragma unroll
    for (int s = 0; s < 2; s++) {
        const int k0 = s << 5;
        #pragma unroll
        for (int i = 0; i < 4; i++) {
            cp16(&Qs[s * SCQ_ + (rL + i * 32) * 36 + kcL],
                 &qb[(size_t)(rL + i * 32) * LDQKV_ + k0 + kcL]);
            cp16(&Ks[s * SCQ_ + (rL + i * 32) * 36 + kcL],
                 &kb[(size_t)(rL + i * 32) * LDQKV_ + k0 + kcL]);
        }
        CP_COMMIT();
    }

    float c[2][8][4] = {};
    #pragma unroll
    for (int s = 0; s < 2; s++) {
        if (s == 0) CP_WAIT1(); else CP_WAIT0();
        __syncthreads();
        const uint32_t sQ = sQ0 + s * SCQ_ * 4;
        const uint32_t sK = sK0 + s * SCQ_ * 4;
        #pragma unroll
        for (int ks = 0; ks < 32; ks += 8) {
            unsigned a[2][4], bfr[8][2];
            #pragma unroll
            for (int i = 0; i < 2; i++)
                ldsm_x4(a[i][0], a[i][1], a[i][2], a[i][3],
                        sQ + (uint32_t)(((a_row + i * 16) * 36 + ks + a_col) * 4));
            #pragma unroll
            for (int jj = 0; jj < 4; jj++)
                ldsm_x4(bfr[2 * jj][0], bfr[2 * jj][1], bfr[2 * jj + 1][0], bfr[2 * jj + 1][1],
                        sK + (uint32_t)(((wn + jj * 16 + b_row) * 36 + ks + b_col) * 4));
            #pragma unroll
            for (int i = 0; i < 2; i++)
                #pragma unroll
                for (int j = 0; j < 8; j++)
                    mma_tf32(c[i][j], a[i][0], a[i][1], a[i][2], a[i][3], bfr[j][0], bfr[j][1]);
        }
    }

    const bool diag = (kt == qt);
    float rsum[2][2] = {};
    float* ob = attnP + ((size_t)bh * S_ + qt * 128) * S_ + kt * 128;
    #pragma unroll
    for (int i = 0; i < 2; i++)
        #pragma unroll
        for (int j = 0; j < 8; j++) {
            int col = wn + j * 8 + tg * 2;
            #pragma unroll
            for (int hh = 0; hh < 2; hh++) {
                int row = wm + i * 16 + g + hh * 8;
                float v0 = __expf(c[i][j][hh * 2 + 0] * 0.03125f);
                float v1 = __expf(c[i][j][hh * 2 + 1] * 0.03125f);
                if (diag) {
                    if (col     > row) v0 = 0.f;
                    if (col + 1 > row) v1 = 0.f;
                }
                rsum[i][hh] += v0 + v1;
                *(float2*)&ob[(size_t)row * S_ + col] = make_float2(v0, v1);
            }
        }

    #pragma unroll
    for (int i = 0; i < 2; i++)
        #pragma unroll
        for (int hh = 0; hh < 2; hh++) {
            rsum[i][hh] += __shfl_xor_sync(0xffffffff, rsum[i][hh], 1);
            rsum[i][hh] += __shfl_xor_sync(0xffffffff, rsum[i][hh], 2);
        }
    __syncthreads();
    float* psm = (float*)Qs;
    if (tg == 0) {
        #pragma unroll
        for (int i = 0; i < 2; i++)
            #pragma unroll
            for (int hh = 0; hh < 2; hh++)
                psm[(wm + i * 16 + g + hh * 8) * 2 + (wn >> 6)] = rsum[i][hh];
    }
    __syncthreads();
    if (tid < 128)
        rs[((size_t)bh * S_ + qt * 128 + tid) * NKT_ + kt] = psm[tid * 2] + psm[tid * 2 + 1];
}

// =====================================================================
// ctx = (P' @ V) * inv; inv computed in-block from rs partials.
// K-tile 32; normalized write-back from smem. Longest-first qt.
// =====================================================================
__global__ __launch_bounds__(256, 2)
void attn_pv_norm(float* __restrict__ attnP, const float* __restrict__ QKV,
                  const float* __restrict__ rs, float* __restrict__ Ctx) {
    const int qt = NKT_ - 1 - blockIdx.x, bh = blockIdx.y;
    const int b = bh >> 4, h = bh & 15;

    __shared__ unsigned As[2][128][36];
    __shared__ unsigned Bs[2][32][72];
    __shared__ float sinv[128];
    const uint32_t sAbase = smem_u32(&As[0][0][0]);

    const int tid = threadIdx.x;
    const int warp = tid >> 5, lane = tid & 31;
    const int g = lane >> 2, tg = lane & 3;
    const int wm = (warp >> 1) * 32, wn = (warp & 1) * 32;

    const int a_row = wm + (lane & 15);
    const int a_col = (lane >> 4) * 4;

    float* Ab = attnP + ((size_t)bh * S_ + qt * 128) * S_;
    const float* Vb = QKV + (size_t)(b * S_) * LDQKV_ + 2048 + h * DEPTH_;

    const int rL = tid >> 3, kcL = (tid & 7) * 4;
    const int vR = tid >> 4, vC = (tid & 15) * 4;

    // in-block inv computation (same summation order as old rowsum_inv)
    if (tid < 128) {
        const float* rsrow = rs + ((size_t)bh * S_ + qt * 128 + tid) * NKT_;
        float s = 0.f;
        for (int kt = 0; kt <= qt; kt++) s += rsrow[kt];
        sinv[tid] = 1.0f / s;
    }

    float c[2][4][4] = {};
    const int T = (qt + 1) * 4;

    #pragma unroll
    for (int i = 0; i < 4; i++)
        cp16(&As[0][rL + i * 32][kcL], &Ab[(size_t)(rL + i * 32) * S_ + kcL]);
    #pragma unroll
    for (int i = 0; i < 2; i++)
        cp16(&Bs[0][vR + i * 16][vC], &Vb[(size_t)(vR + i * 16) * LDQKV_ + vC]);
    CP_COMMIT();
    __syncthreads();                       // sinv visible to all

    float ivA[4];
    #pragma unroll
    for (int i = 0; i < 4; i++) ivA[i] = sinv[rL + i * 32];

    for (int t = 0; t < T; t++) {
        if (t + 1 < T) {
            const int k0 = (t + 1) << 5, st = (t + 1) & 1;
            #pragma unroll
            for (int i = 0; i < 4; i++)
                cp16(&As[st][rL + i * 32][kcL], &Ab[(size_t)(rL + i * 32) * S_ + k0 + kcL]);
            #pragma unroll
            for (int i = 0; i < 2; i++)
                cp16(&Bs[st][vR + i * 16][vC], &Vb[(size_t)(k0 + vR + i * 16) * LDQKV_ + vC]);
            CP_COMMIT();
            CP_WAIT1();
        } else {
            CP_WAIT0();
        }
        __syncthreads();
        const int st = t & 1;
        const uint32_t sA = sAbase + (uint32_t)(st * 128 * 36 * 4);
        #pragma unroll
        for (int ks = 0; ks < 32; ks += 8) {
            unsigned a[2][4], bfr[4][2];
            #pragma unroll
            for (int i = 0; i < 2; i++)
                ldsm_x4(a[i][0], a[i][1], a[i][2], a[i][3],
                        sA + (uint32_t)(((a_row + i * 16) * 36 + ks + a_col) * 4));
            #pragma unroll
            for (int j = 0; j < 4; j++) {
                int nB = wn + j * 8;
                bfr[j][0] = Bs[st][ks + tg    ][nB + g];
                bfr[j][1] = Bs[st][ks + tg + 4][nB + g];
            }
            #pragma unroll
            for (int i = 0; i < 2; i++)
                #pragma unroll
                for (int j = 0; j < 4; j++)
                    mma_tf32(c[i][j], a[i][0], a[i][1], a[i][2], a[i][3], bfr[j][0], bfr[j][1]);
        }
        #pragma unroll
        for (int i = 0; i < 4; i++) {
            float4 p = *(float4*)&As[st][rL + i * 32][kcL];
            *(float4*)&Ab[(size_t)(rL + i * 32) * S_ + t * 32 + kcL] =
                make_float4(p.x * ivA[i], p.y * ivA[i], p.z * ivA[i], p.w * ivA[i]);
        }
    }

    float ivr[2][2];
    #pragma unroll
    for (int i = 0; i < 2; i++)
        #pragma unroll
        for (int hh = 0; hh < 2; hh++)
            ivr[i][hh] = sinv[wm + i * 16 + g + hh * 8];

    #pragma unroll
    for (int i = 0; i < 2; i++)
        #pragma unroll
        for (int j = 0; j < 4; j++) {
            int col = wn + j * 8 + tg * 2;
            #pragma unroll
            for (int hh = 0; hh < 2; hh++) {
                int row = qt * 128 + wm + i * 16 + g + hh * 8;
                int t = b * S_ + row;
                *(float2*)&Ctx[(size_t)t * D_ + h * DEPTH_ + col] =
                    make_float2(roundtf(c[i][j][hh * 2 + 0] * ivr[i][hh]),
                                roundtf(c[i][j][hh * 2 + 1] * ivr[i][hh]));
            }
        }
}

// ---------------- fused residual + LayerNorm (shfl reductions) ----------------
template <int WRITE_ROUND>
__global__ void ln_residual(const float* __restrict__ a, const float* __restrict__ bb,
                            const float* __restrict__ g, const float* __restrict__ be,
                            float* __restrict__ out, float* __restrict__ outr) {
    const int t = blockIdx.x;
    const int tid = threadIdx.x;
    const int lane = tid & 31, warp = tid >> 5;
    float4 va = ((const float4*)(a  + (size_t)t * D_))[tid];
    float4 vb = ((const float4*)(bb + (size_t)t * D_))[tid];
    float4 v = make_float4(va.x + vb.x, va.y + vb.y, va.z + vb.z, va.w + vb.w);

    __shared__ float sm[16];
    float s = v.x + v.y + v.z + v.w;
    #pragma unroll
    for (int o = 16; o > 0; o >>= 1) s += __shfl_xor_sync(0xffffffff, s, o);
    if (lane == 0) sm[warp] = s;
    __syncthreads();
    float mu;
    {
        float w = sm[lane & 7];
        #pragma unroll
        for (int o = 4; o > 0; o >>= 1) w += __shfl_xor_sync(0xffffffff, w, o);
        mu = w * (1.0f / D_);
    }

    float dx = v.x - mu, dy = v.y - mu, dz = v.z - mu, dw = v.w - mu;
    float s2 = dx * dx + dy * dy + dz * dz + dw * dw;
    #pragma unroll
    for (int o = 16; o > 0; o >>= 1) s2 += __shfl_xor_sync(0xffffffff, s2, o);
    __syncthreads();
    if (lane == 0) sm[8 + warp] = s2;
    __syncthreads();
    float inv;
    {
        float w = sm[8 + (lane & 7)];
        #pragma unroll
        for (int o = 4; o > 0; o >>= 1) w += __shfl_xor_sync(0xffffffff, w, o);
        inv = rsqrtf(w * (1.0f / D_) + EPS_);
    }

    float4 gg = ((const float4*)g)[tid];
    float4 bz = ((const float4*)be)[tid];
    float4 o = make_float4(dx * inv * gg.x + bz.x, dy * inv * gg.y + bz.y,
                           dz * inv * gg.z + bz.z, dw * inv * gg.w + bz.w);
    ((float4*)(out + (size_t)t * D_))[tid] = o;
    if (WRITE_ROUND) {
        float4 orr = make_float4(roundtf(o.x), roundtf(o.y), roundtf(o.z), roundtf(o.w));
        ((float4*)(outr + (size_t)t * D_))[tid] = orr;
    }
}

// ---------------- launch ----------------
extern "C" void kernel_launch(void* const* d_in, const int* in_sizes, int n_in,
                              void* d_out, int out_size) {
    const float* x  = (const float*)d_in[0];
    const float* Wq = (const float*)d_in[2];  const float* bq = (const float*)d_in[3];
    const float* Wk = (const float*)d_in[4];  const float* bk = (const float*)d_in[5];
    const float* Wv = (const float*)d_in[6];  const float* bv = (const float*)d_in[7];
    const float* Wo = (const float*)d_in[8];  const float* bo = (const float*)d_in[9];
    const float* W1 = (const float*)d_in[10]; const float* b1 = (const float*)d_in[11];
    const float* W2 = (const float*)d_in[12]; const float* b2 = (const float*)d_in[13];
    const float* ln1g = (const float*)d_in[14]; const float* ln1b = (const float*)d_in[15];
    const float* ln2g = (const float*)d_in[16]; const float* ln2b = (const float*)d_in[17];

    float* out  = (float*)d_out;
    float* attn = out + (size_t)NT_ * D_;

    float *qkv, *wcat, *bcat, *ctx, *ao, *x1, *x1r, *h1, *ff2, *xr, *wr, *rs;
    cudaGetSymbolAddress((void**)&qkv,  g_qkv);
    cudaGetSymbolAddress((void**)&wcat, g_wcat);
    cudaGetSymbolAddress((void**)&bcat, g_bcat);
    cudaGetSymbolAddress((void**)&ctx,  g_ctx);
    cudaGetSymbolAddress((void**)&ao,   g_ao);
    cudaGetSymbolAddress((void**)&x1,   g_x1);
    cudaGetSymbolAddress((void**)&x1r,  g_x1r);
    cudaGetSymbolAddress((void**)&h1,   g_h1);
    cudaGetSymbolAddress((void**)&ff2,  g_ff2);
    cudaGetSymbolAddress((void**)&xr,   g_xr);
    cudaGetSymbolAddress((void**)&wr,   g_wr);
    cudaGetSymbolAddress((void**)&rs,   g_rs);

    float* WqkvT = wcat;
    float* WoT   = wr;
    float* W1T   = wr + 1048576;
    float* W2T   = wr + 5242880;

    const int GEMM_SMEM = 2 * (ASZ_ + BSZ_) * 4;       // 73728
    const int SC_SMEM   = 4 * SCQ_ * 4;                // 73728
    cudaFuncSetAttribute(gemm_tf32p<0,1>, cudaFuncAttributeMaxDynamicSharedMemorySize, GEMM_SMEM);
    cudaFuncSetAttribute(gemm_tf32p<0,0>, cudaFuncAttributeMaxDynamicSharedMemorySize, GEMM_SMEM);
    cudaFuncSetAttribute(gemm_tf32p<1,1>, cudaFuncAttributeMaxDynamicSharedMemorySize, GEMM_SMEM);
    cudaFuncSetAttribute(attn_scores_exp, cudaFuncAttributeMaxDynamicSharedMemorySize, SC_SMEM);

    dim3 blk(256);
    dim3 tblk(32, 8);

    prep_all<<<16384, tblk>>>(Wq, Wk, Wv, Wo, W1, W2, x, WqkvT, WoT, W1T, W2T, xr);
    cudaMemcpyAsync(bcat,        bq, D_ * 4, cudaMemcpyDeviceToDevice);
    cudaMemcpyAsync(bcat + 1024, bk, D_ * 4, cudaMemcpyDeviceToDevice);
    cudaMemcpyAsync(bcat + 2048, bv, D_ * 4, cudaMemcpyDeviceToDevice);

    dim3 gQKV(LDQKV_ / 128, NT_ / 128);         // (24, 32)
    gemm_tf32p<0,1><<<gQKV, blk, GEMM_SMEM>>>(xr, WqkvT, bcat, qkv, NT_, LDQKV_, D_);

    dim3 gScore(S_ / 128, S_ / 128, B_ * H_);   // (16, 16, 32)
    attn_scores_exp<<<gScore, blk, SC_SMEM>>>(qkv, attn, rs);

    dim3 gPV(S_ / 128, B_ * H_);                // (16, 32)
    attn_pv_norm<<<gPV, blk>>>(attn, qkv, rs, ctx);

    dim3 gProj(D_ / 128, NT_ / 128);            // (8, 32)
    gemm_tf32p<0,0><<<gProj, blk, GEMM_SMEM>>>(ctx, WoT, bo, ao, NT_, D_, D_);
    ln_residual<1><<<NT_, blk>>>(x, ao, ln1g, ln1b, x1, x1r);

    dim3 gFF1(DFF_ / 128, NT_ / 128);           // (32, 32)
    gemm_tf32p<1,1><<<gFF1, blk, GEMM_SMEM>>>(x1r, W1T, b1, h1, NT_, DFF_, D_);
    gemm_tf32p<0,0><<<gProj, blk, GEMM_SMEM>>>(h1, W2T, b2, ff2, NT_, D_, DFF_);
    ln_residual<0><<<NT_, blk>>>(x1, ff2, ln2g, ln2b, out, nullptr);
}

// round 17
// speedup vs baseline: 1.0034x; 1.0034x over previous
#include <cuda_runtime.h>
#include <math.h>
#include <stdint.h>

#define B_ 2
#define S_ 2048
#define D_ 1024
#define H_ 16
#define DEPTH_ 64
#define DFF_ 4096
#define NT_ (B_ * S_)
#define EPS_ 1e-5f
#define LDQKV_ 3072
#define NROWS_ (B_ * H_ * S_)
#define NKT_ 16

// ---------------- scratch ----------------
__device__ float g_qkv[NT_ * LDQKV_];
__device__ float g_wcat[D_ * LDQKV_];   // WqkvT [3072][1024]
__device__ float g_bcat[LDQKV_];
__device__ float g_ctx[NT_ * D_];
__device__ float g_ao [NT_ * D_];
__device__ float g_x1 [NT_ * D_];
__device__ float g_x1r[NT_ * D_];
__device__ float g_h1 [NT_ * DFF_];
__device__ float g_ff2[NT_ * D_];
__device__ float g_xr [NT_ * D_];
__device__ float g_wr [9437184];        // WoT(1M) W1T(4M) W2T(4M)
__device__ float g_rs [NROWS_ * NKT_];

// ---------------- helpers ----------------
__device__ __forceinline__ unsigned f2tf(float x) {
    unsigned r;
    asm("cvt.rna.tf32.f32 %0, %1;" : "=r"(r) : "f"(x));
    return r;
}
__device__ __forceinline__ float roundtf(float x) { return __uint_as_float(f2tf(x)); }

__device__ __forceinline__ void mma_tf32(float c[4],
                                         unsigned a0, unsigned a1, unsigned a2, unsigned a3,
                                         unsigned b0, unsigned b1) {
    asm volatile(
        "mma.sync.aligned.m16n8k8.row.col.f32.tf32.tf32.f32 "
        "{%0,%1,%2,%3},{%4,%5,%6,%7},{%8,%9},{%0,%1,%2,%3};\n"
        : "+f"(c[0]), "+f"(c[1]), "+f"(c[2]), "+f"(c[3])
        : "r"(a0), "r"(a1), "r"(a2), "r"(a3), "r"(b0), "r"(b1));
}

__device__ __forceinline__ void ldsm_x4(unsigned &r0, unsigned &r1, unsigned &r2, unsigned &r3,
                                        uint32_t addr) {
    asm volatile("ldmatrix.sync.aligned.m8n8.x4.shared.b16 {%0,%1,%2,%3}, [%4];"
                 : "=r"(r0), "=r"(r1), "=r"(r2), "=r"(r3) : "r"(addr));
}

__device__ __forceinline__ void cp16(void* smem, const void* gmem) {
    unsigned sa = (unsigned)__cvta_generic_to_shared(smem);
    asm volatile("cp.async.cg.shared.global [%0], [%1], 16;\n" :: "r"(sa), "l"(gmem));
}
#define CP_COMMIT() asm volatile("cp.async.commit_group;\n" ::)
#define CP_WAIT1()  asm volatile("cp.async.wait_group 1;\n" ::)
#define CP_WAIT0()  asm volatile("cp.async.wait_group 0;\n" ::)

__device__ __forceinline__ uint32_t smem_u32(const void* p) {
    return (uint32_t)__cvta_generic_to_shared(p);
}

// ---------------- pre-passes (R13 versions) ----------------
__global__ void round_copy(const float* __restrict__ src, float* __restrict__ dst, int n4) {
    int i = blockIdx.x * 256 + threadIdx.x;
    if (i < n4) {
        float4 t = ((const float4*)src)[i];
        t.x = roundtf(t.x); t.y = roundtf(t.y); t.z = roundtf(t.z); t.w = roundtf(t.w);
        ((float4*)dst)[i] = t;
    }
}
__global__ void round_T(const float* __restrict__ src, float* __restrict__ dst, int R, int C) {
    __shared__ float t[32][33];
    int c0 = blockIdx.x * 32, r0 = blockIdx.y * 32;
    int tx = threadIdx.x, ty = threadIdx.y;
    #pragma unroll
    for (int i = 0; i < 4; i++)
        t[ty + i * 8][tx] = src[(size_t)(r0 + ty + i * 8) * C + c0 + tx];
    __syncthreads();
    #pragma unroll
    for (int i = 0; i < 4; i++)
        dst[(size_t)(c0 + ty + i * 8) * R + r0 + tx] = roundtf(t[tx][ty + i * 8]);
}

// =====================================================================
// Dense GEMM: K-tile 32, 2-stage cp.async, 128x128, ldmatrix. (R12/R13)
// =====================================================================
#define ASZ_ 4608
#define BSZ_ 4608
#define LDK_ 36
template <int GELU, int ROUND>
__global__ __launch_bounds__(256, 2)
void gemm_tf32p(const float* __restrict__ A, const float* __restrict__ Bt,
                const float* __restrict__ bias, float* __restrict__ C,
                int M, int N, int K) {
    extern __shared__ unsigned dsm[];
    unsigned* Asp = dsm;
    unsigned* Bsp = dsm + 2 * ASZ_;
    const uint32_t sA0 = smem_u32(Asp), sB0 = smem_u32(Bsp);

    const int tid = threadIdx.x;
    const int warp = tid >> 5, lane = tid & 31;
    const int g = lane >> 2, tg = lane & 3;
    const int m0 = blockIdx.y * 128, n0 = blockIdx.x * 128;
    const int wm = (warp >> 1) * 32, wn = (warp & 1) * 64;

    const int a_row = wm + (lane & 15);
    const int a_col = (lane >> 4) * 4;
    const int b_row = (lane & 7) + ((lane >> 4) & 1) * 8;
    const int b_col = ((lane >> 3) & 1) * 4;

    const int rL = tid >> 3, kcL = (tid & 7) * 4;

    float c[2][8][4] = {};
    const int T = K >> 5;

    #pragma unroll
    for (int i = 0; i < 4; i++) {
        cp16(&Asp[(rL + i * 32) * LDK_ + kcL], &A[(size_t)(m0 + rL + i * 32) * K + kcL]);
        cp16(&Bsp[(rL + i * 32) * LDK_ + kcL], &Bt[(size_t)(n0 + rL + i * 32) * K + kcL]);
    }
    CP_COMMIT();

    for (int t = 0; t < T; t++) {
        if (t + 1 < T) {
            const int s = (t + 1) & 1, k0 = (t + 1) << 5;
            #pragma unroll
            for (int i = 0; i < 4; i++) {
                cp16(&Asp[s * ASZ_ + (rL + i * 32) * LDK_ + kcL],
                     &A[(size_t)(m0 + rL + i * 32) * K + k0 + kcL]);
                cp16(&Bsp[s * BSZ_ + (rL + i * 32) * LDK_ + kcL],
                     &Bt[(size_t)(n0 + rL + i * 32) * K + k0 + kcL]);
            }
            CP_COMMIT();
            CP_WAIT1();
        } else {
            CP_WAIT0();
        }
        __syncthreads();
        const uint32_t sA = sA0 + (t & 1) * ASZ_ * 4;
        const uint32_t sB = sB0 + (t & 1) * BSZ_ * 4;
        #pragma unroll
        for (int ks = 0; ks < 32; ks += 8) {
            unsigned a[2][4], b[8][2];
            #pragma unroll
            for (int i = 0; i < 2; i++)
                ldsm_x4(a[i][0], a[i][1], a[i][2], a[i][3],
                        sA + (uint32_t)(((a_row + i * 16) * LDK_ + ks + a_col) * 4));
            #pragma unroll
            for (int jj = 0; jj < 4; jj++)
                ldsm_x4(b[2 * jj][0], b[2 * jj][1], b[2 * jj + 1][0], b[2 * jj + 1][1],
                        sB + (uint32_t)(((wn + jj * 16 + b_row) * LDK_ + ks + b_col) * 4));
            #pragma unroll
            for (int i = 0; i < 2; i++)
                #pragma unroll
                for (int j = 0; j < 8; j++)
                    mma_tf32(c[i][j], a[i][0], a[i][1], a[i][2], a[i][3], b[j][0], b[j][1]);
        }
        __syncthreads();
    }

    #pragma unroll
    for (int i = 0; i < 2; i++) {
        #pragma unroll
        for (int j = 0; j < 8; j++) {
            int col = n0 + wn + j * 8 + tg * 2;
            float b0v = bias[col], b1v = bias[col + 1];
            #pragma unroll
            for (int h = 0; h < 2; h++) {
                int row = m0 + wm + i * 16 + g + h * 8;
                float v0 = c[i][j][h * 2 + 0] + b0v;
                float v1 = c[i][j][h * 2 + 1] + b1v;
                if (GELU) {
                    v0 = 0.5f * v0 * (1.0f + erff(v0 * 0.70710678118654752f));
                    v1 = 0.5f * v1 * (1.0f + erff(v1 * 0.70710678118654752f));
                }
                if (ROUND) { v0 = roundtf(v0); v1 = roundtf(v1); }
                *(float2*)&C[(size_t)row * N + col] = make_float2(v0, v1);
            }
        }
    }
}

// =====================================================================
// Scores + exp + partial row sums; kt>qt blocks zero-fill. (R13 version)
// =====================================================================
__global__ __launch_bounds__(256, 2)
void attn_scores_exp(const float* __restrict__ QKV, float* __restrict__ attnP,
                     float* __restrict__ rs) {
    const int kt = blockIdx.x, qt = blockIdx.y, bh = blockIdx.z;
    const int tid = threadIdx.x;

    if (kt > qt) {
        float4 z = make_float4(0.f, 0.f, 0.f, 0.f);
        float* tb = attnP + ((size_t)bh * S_ + qt * 128) * S_ + kt * 128;
        #pragma unroll
        for (int e = 0; e < 16; e++) {
            int u = tid + e * 256;
            int r = u >> 5, c4 = u & 31;
            ((float4*)(tb + (size_t)r * S_))[c4] = z;
        }
        return;
    }

    const int b = bh >> 4, h = bh & 15;

    extern __shared__ unsigned dsm[];
    unsigned* Qs = dsm;              // [128][68]
    unsigned* Ks = dsm + 128 * 68;
    const uint32_t sQ = smem_u32(Qs), sK = smem_u32(Ks);

    const int warp = tid >> 5, lane = tid & 31;
    const int g = lane >> 2, tg = lane & 3;
    const int wm = (warp >> 1) * 32, wn = (warp & 1) * 64;

    const int a_row = wm + (lane & 15);
    const int a_col = (lane >> 4) * 4;
    const int b_row = (lane & 7) + ((lane >> 4) & 1) * 8;
    const int b_col = ((lane >> 3) & 1) * 4;

    const float* qb = QKV + (size_t)(b * S_ + qt * 128) * LDQKV_ + h * DEPTH_;
    const float* kb = QKV + (size_t)(b * S_ + kt * 128) * LDQKV_ + 1024 + h * DEPTH_;

    #pragma unroll
    for (int e = 0; e < 8; e++) {
        int u = tid + e * 256;
        int r = u >> 4, cc = (u & 15) * 4;
        cp16(&Qs[r * 68 + cc], &qb[(size_t)r * LDQKV_ + cc]);
        cp16(&Ks[r * 68 + cc], &kb[(size_t)r * LDQKV_ + cc]);
    }
    CP_COMMIT();
    CP_WAIT0();
    __syncthreads();

    float c[2][8][4] = {};
    #pragma unroll
    for (int ks = 0; ks < 64; ks += 8) {
        unsigned a[2][4], bfr[8][2];
        #pragma unroll
        for (int i = 0; i < 2; i++)
            ldsm_x4(a[i][0], a[i][1], a[i][2], a[i][3],
                    sQ + (uint32_t)(((a_row + i * 16) * 68 + ks + a_col) * 4));
        #pragma unroll
        for (int jj = 0; jj < 4; jj++)
            ldsm_x4(bfr[2 * jj][0], bfr[2 * jj][1], bfr[2 * jj + 1][0], bfr[2 * jj + 1][1],
                    sK + (uint32_t)(((wn + jj * 16 + b_row) * 68 + ks + b_col) * 4));
        #pragma unroll
        for (int i = 0; i < 2; i++)
            #pragma unroll
            for (int j = 0; j < 8; j++)
                mma_tf32(c[i][j], a[i][0], a[i][1], a[i][2], a[i][3], bfr[j][0], bfr[j][1]);
    }

    const bool diag = (kt == qt);
    float rsum[2][2] = {};
    float* ob = attnP + ((size_t)bh * S_ + qt * 128) * S_ + kt * 128;
    #pragma unroll
    for (int i = 0; i < 2; i++)
        #pragma unroll
        for (int j = 0; j < 8; j++) {
            int col = wn + j * 8 + tg * 2;
            #pragma unroll
            for (int hh = 0; hh < 2; hh++) {
                int row = wm + i * 16 + g + hh * 8;
                float v0 = __expf(c[i][j][hh * 2 + 0] * 0.03125f);
                float v1 = __expf(c[i][j][hh * 2 + 1] * 0.03125f);
                if (diag) {
                    if (col     > row) v0 = 0.f;
                    if (col + 1 > row) v1 = 0.f;
                }
                rsum[i][hh] += v0 + v1;
                *(float2*)&ob[(size_t)row * S_ + col] = make_float2(v0, v1);
            }
        }

    #pragma unroll
    for (int i = 0; i < 2; i++)
        #pragma unroll
        for (int hh = 0; hh < 2; hh++) {
            rsum[i][hh] += __shfl_xor_sync(0xffffffff, rsum[i][hh], 1);
            rsum[i][hh] += __shfl_xor_sync(0xffffffff, rsum[i][hh], 2);
        }
    __syncthreads();
    float* psm = (float*)Qs;
    if (tg == 0) {
        #pragma unroll
        for (int i = 0; i < 2; i++)
            #pragma unroll
            for (int hh = 0; hh < 2; hh++)
                psm[(wm + i * 16 + g + hh * 8) * 2 + (wn >> 6)] = rsum[i][hh];
    }
    __syncthreads();
    if (tid < 128)
        rs[((size_t)bh * S_ + qt * 128 + tid) * NKT_ + kt] = psm[tid * 2] + psm[tid * 2 + 1];
}

// =====================================================================
// ctx = (P' @ V) * inv; inv computed in-block from rs partials (same
// summation order as R13's rowsum_inv). K-tile 32; normalized write-back
// from smem. Longest-first qt. (R13 PV + in-block inv)
// =====================================================================
__global__ __launch_bounds__(256, 2)
void attn_pv_norm(float* __restrict__ attnP, const float* __restrict__ QKV,
                  const float* __restrict__ rs, float* __restrict__ Ctx) {
    const int qt = NKT_ - 1 - blockIdx.x, bh = blockIdx.y;
    const int b = bh >> 4, h = bh & 15;

    __shared__ unsigned As[2][128][36];
    __shared__ unsigned Bs[2][32][72];
    __shared__ float sinv[128];
    const uint32_t sAbase = smem_u32(&As[0][0][0]);

    const int tid = threadIdx.x;
    const int warp = tid >> 5, lane = tid & 31;
    const int g = lane >> 2, tg = lane & 3;
    const int wm = (warp >> 1) * 32, wn = (warp & 1) * 32;

    const int a_row = wm + (lane & 15);
    const int a_col = (lane >> 4) * 4;

    float* Ab = attnP + ((size_t)bh * S_ + qt * 128) * S_;
    const float* Vb = QKV + (size_t)(b * S_) * LDQKV_ + 2048 + h * DEPTH_;

    const int rL = tid >> 3, kcL = (tid & 7) * 4;
    const int vR = tid >> 4, vC = (tid & 15) * 4;

    if (tid < 128) {
        const float* rsrow = rs + ((size_t)bh * S_ + qt * 128 + tid) * NKT_;
        float s = 0.f;
        for (int kt = 0; kt <= qt; kt++) s += rsrow[kt];
        sinv[tid] = 1.0f / s;
    }

    float c[2][4][4] = {};
    const int T = (qt + 1) * 4;

    #pragma unroll
    for (int i = 0; i < 4; i++)
        cp16(&As[0][rL + i * 32][kcL], &Ab[(size_t)(rL + i * 32) * S_ + kcL]);
    #pragma unroll
    for (int i = 0; i < 2; i++)
        cp16(&Bs[0][vR + i * 16][vC], &Vb[(size_t)(vR + i * 16) * LDQKV_ + vC]);
    CP_COMMIT();
    __syncthreads();                       // sinv visible

    float ivA[4];
    #pragma unroll
    for (int i = 0; i < 4; i++) ivA[i] = sinv[rL + i * 32];

    for (int t = 0; t < T; t++) {
        if (t + 1 < T) {
            const int k0 = (t + 1) << 5, st = (t + 1) & 1;
            #pragma unroll
            for (int i = 0; i < 4; i++)
                cp16(&As[st][rL + i * 32][kcL], &Ab[(size_t)(rL + i * 32) * S_ + k0 + kcL]);
            #pragma unroll
            for (int i = 0; i < 2; i++)
                cp16(&Bs[st][vR + i * 16][vC], &Vb[(size_t)(k0 + vR + i * 16) * LDQKV_ + vC]);
            CP_COMMIT();
            CP_WAIT1();
        } else {
            CP_WAIT0();
        }
        __syncthreads();
        const int st = t & 1;
        const uint32_t sA = sAbase + (uint32_t)(st * 128 * 36 * 4);
        #pragma unroll
        for (int ks = 0; ks < 32; ks += 8) {
            unsigned a[2][4], bfr[4][2];
            #pragma unroll
            for (int i = 0; i < 2; i++)
                ldsm_x4(a[i][0], a[i][1], a[i][2], a[i][3],
                        sA + (uint32_t)(((a_row + i * 16) * 36 + ks + a_col) * 4));
            #pragma unroll
            for (int j = 0; j < 4; j++) {
                int nB = wn + j * 8;
                bfr[j][0] = Bs[st][ks + tg    ][nB + g];
                bfr[j][1] = Bs[st][ks + tg + 4][nB + g];
            }
            #pragma unroll
            for (int i = 0; i < 2; i++)
                #pragma unroll
                for (int j = 0; j < 4; j++)
                    mma_tf32(c[i][j], a[i][0], a[i][1], a[i][2], a[i][3], bfr[j][0], bfr[j][1]);
        }
        #pragma unroll
        for (int i = 0; i < 4; i++) {
            float4 p = *(float4*)&As[st][rL + i * 32][kcL];
            *(float4*)&Ab[(size_t)(rL + i * 32) * S_ + t * 32 + kcL] =
                make_float4(p.x * ivA[i], p.y * ivA[i], p.z * ivA[i], p.w * ivA[i]);
        }
    }

    float ivr[2][2];
    #pragma unroll
    for (int i = 0; i < 2; i++)
        #pragma unroll
        for (int hh = 0; hh < 2; hh++)
            ivr[i][hh] = sinv[wm + i * 16 + g + hh * 8];

    #pragma unroll
    for (int i = 0; i < 2; i++)
        #pragma unroll
        for (int j = 0; j < 4; j++) {
            int col = wn + j * 8 + tg * 2;
            #pragma unroll
            for (int hh = 0; hh < 2; hh++) {
                int row = qt * 128 + wm + i * 16 + g + hh * 8;
                int t = b * S_ + row;
                *(float2*)&Ctx[(size_t)t * D_ + h * DEPTH_ + col] =
                    make_float2(roundtf(c[i][j][hh * 2 + 0] * ivr[i][hh]),
                                roundtf(c[i][j][hh * 2 + 1] * ivr[i][hh]));
            }
        }
}

// ---------------- fused residual + LayerNorm (R13 tree version) ----------------
template <int WRITE_ROUND>
__global__ void ln_residual(const float* __restrict__ a, const float* __restrict__ bb,
                            const float* __restrict__ g, const float* __restrict__ be,
                            float* __restrict__ out, float* __restrict__ outr) {
    const int t = blockIdx.x;
    const int tid = threadIdx.x;
    float4 va = ((const float4*)(a  + (size_t)t * D_))[tid];
    float4 vb = ((const float4*)(bb + (size_t)t * D_))[tid];
    float4 v = make_float4(va.x + vb.x, va.y + vb.y, va.z + vb.z, va.w + vb.w);

    __shared__ float sm[256];
    sm[tid] = v.x + v.y + v.z + v.w; __syncthreads();
    for (int st = 128; st > 0; st >>= 1) { if (tid < st) sm[tid] += sm[tid + st]; __syncthreads(); }
    const float mu = sm[0] * (1.0f / D_);
    __syncthreads();

    float dx = v.x - mu, dy = v.y - mu, dz = v.z - mu, dw = v.w - mu;
    sm[tid] = dx * dx + dy * dy + dz * dz + dw * dw; __syncthreads();
    for (int st = 128; st > 0; st >>= 1) { if (tid < st) sm[tid] += sm[tid + st]; __syncthreads(); }
    const float inv = rsqrtf(sm[0] * (1.0f / D_) + EPS_);

    float4 gg = ((const float4*)g)[tid];
    float4 bz = ((const float4*)be)[tid];
    float4 o = make_float4(dx * inv * gg.x + bz.x, dy * inv * gg.y + bz.y,
                           dz * inv * gg.z + bz.z, dw * inv * gg.w + bz.w);
    ((float4*)(out + (size_t)t * D_))[tid] = o;
    if (WRITE_ROUND) {
        float4 orr = make_float4(roundtf(o.x), roundtf(o.y), roundtf(o.z), roundtf(o.w));
        ((float4*)(outr + (size_t)t * D_))[tid] = orr;
    }
}

// ---------------- launch ----------------
extern "C" void kernel_launch(void* const* d_in, const int* in_sizes, int n_in,
                              void* d_out, int out_size) {
    const float* x  = (const float*)d_in[0];
    const float* Wq = (const float*)d_in[2];  const float* bq = (const float*)d_in[3];
    const float* Wk = (const float*)d_in[4];  const float* bk = (const float*)d_in[5];
    const float* Wv = (const float*)d_in[6];  const float* bv = (const float*)d_in[7];
    const float* Wo = (const float*)d_in[8];  const float* bo = (const float*)d_in[9];
    const float* W1 = (const float*)d_in[10]; const float* b1 = (const float*)d_in[11];
    const float* W2 = (const float*)d_in[12]; const float* b2 = (const float*)d_in[13];
    const float* ln1g = (const float*)d_in[14]; const float* ln1b = (const float*)d_in[15];
    const float* ln2g = (const float*)d_in[16]; const float* ln2b = (const float*)d_in[17];

    float* out  = (float*)d_out;
    float* attn = out + (size_t)NT_ * D_;

    float *qkv, *wcat, *bcat, *ctx, *ao, *x1, *x1r, *h1, *ff2, *xr, *wr, *rs;
    cudaGetSymbolAddress((void**)&qkv,  g_qkv);
    cudaGetSymbolAddress((void**)&wcat, g_wcat);
    cudaGetSymbolAddress((void**)&bcat, g_bcat);
    cudaGetSymbolAddress((void**)&ctx,  g_ctx);
    cudaGetSymbolAddress((void**)&ao,   g_ao);
    cudaGetSymbolAddress((void**)&x1,   g_x1);
    cudaGetSymbolAddress((void**)&x1r,  g_x1r);
    cudaGetSymbolAddress((void**)&h1,   g_h1);
    cudaGetSymbolAddress((void**)&ff2,  g_ff2);
    cudaGetSymbolAddress((void**)&xr,   g_xr);
    cudaGetSymbolAddress((void**)&wr,   g_wr);
    cudaGetSymbolAddress((void**)&rs,   g_rs);

    float* WqkvT = wcat;                     // [3072][1024]
    float* WoT   = wr;                       // [1024][1024]
    float* W1T   = wr + 1048576;             // [4096][1024]
    float* W2T   = wr + 5242880;             // [1024][4096]

    const int GEMM_SMEM = 2 * (ASZ_ + BSZ_) * 4;       // 73728
    const int SC_SMEM   = 2 * 128 * 68 * 4;            // 69632
    cudaFuncSetAttribute(gemm_tf32p<0,1>, cudaFuncAttributeMaxDynamicSharedMemorySize, GEMM_SMEM);
    cudaFuncSetAttribute(gemm_tf32p<0,0>, cudaFuncAttributeMaxDynamicSharedMemorySize, GEMM_SMEM);
    cudaFuncSetAttribute(gemm_tf32p<1,1>, cudaFuncAttributeMaxDynamicSharedMemorySize, GEMM_SMEM);
    cudaFuncSetAttribute(attn_scores_exp, cudaFuncAttributeMaxDynamicSharedMemorySize, SC_SMEM);

    dim3 blk(256);
    dim3 tblk(32, 8);

    // transposed + rna-rounded weights (R13 pre-passes)
    round_T<<<dim3(32, 32),  tblk>>>(Wq, WqkvT,           1024, 1024);
    round_T<<<dim3(32, 32),  tblk>>>(Wk, WqkvT + 1048576, 1024, 1024);
    round_T<<<dim3(32, 32),  tblk>>>(Wv, WqkvT + 2097152, 1024, 1024);
    round_T<<<dim3(32, 32),  tblk>>>(Wo, WoT,             1024, 1024);
    round_T<<<dim3(128, 32), tblk>>>(W1, W1T,             1024, 4096);
    round_T<<<dim3(32, 128), tblk>>>(W2, W2T,             4096, 1024);
    cudaMemcpyAsync(bcat,        bq, D_ * 4, cudaMemcpyDeviceToDevice);
    cudaMemcpyAsync(bcat + 1024, bk, D_ * 4, cudaMemcpyDeviceToDevice);
    cudaMemcpyAsync(bcat + 2048, bv, D_ * 4, cudaMemcpyDeviceToDevice);
    round_copy<<<4096, blk>>>(x, xr, 1048576);

    // fused QKV
    dim3 gQKV(LDQKV_ / 128, NT_ / 128);         // (24, 32)
    gemm_tf32p<0,1><<<gQKV, blk, GEMM_SMEM>>>(xr, WqkvT, bcat, qkv, NT_, LDQKV_, D_);

    dim3 gScore(S_ / 128, S_ / 128, B_ * H_);   // (16, 16, 32)
    attn_scores_exp<<<gScore, blk, SC_SMEM>>>(qkv, attn, rs);

    dim3 gPV(S_ / 128, B_ * H_);                // (16, 32)
    attn_pv_norm<<<gPV, blk>>>(attn, qkv, rs, ctx);

    dim3 gProj(D_ / 128, NT_ / 128);            // (8, 32)
    gemm_tf32p<0,0><<<gProj, blk, GEMM_SMEM>>>(ctx, WoT, bo, ao, NT_, D_, D_);
    ln_residual<1><<<NT_, blk>>>(x, ao, ln1g, ln1b, x1, x1r);

    dim3 gFF1(DFF_ / 128, NT_ / 128);           // (32, 32)
    gemm_tf32p<1,1><<<gFF1, blk, GEMM_SMEM>>>(x1r, W1T, b1, h1, NT_, DFF_, D_);
    gemm_tf32p<0,0><<<gProj, blk, GEMM_SMEM>>>(h1, W2T, b2, ff2, NT_, D_, DFF_);
    ln_residual<0><<<NT_, blk>>>(x1, ff2, ln2g, ln2b, out, nullptr);
}